// round 15
// baseline (speedup 1.0000x reference)
#include <cuda_runtime.h>
#include <cuda_fp16.h>
#include <stdint.h>
#include <math.h>

#define N_NODES 8192
#define H_CH 256
#define HEADS 4
#define HEAD_DIM 64
#define E_EDGES 262144
#define WORDS_PER_ROW (N_NODES / 32)   // 256
#define CAP 256

// ---------------- device scratch ----------------
__device__ __align__(128) __half  g_xh[N_NODES * H_CH];    // x in fp16
__device__ __align__(128) __half  g_wh[4][H_CH * H_CH];    // Wq,Wk,Wv,Wo fp16
__device__ __align__(128) __half  g_qh[N_NODES * H_CH];
__device__ __align__(128) __half  g_kh[N_NODES * H_CH];
__device__ __align__(128) __half  g_vh[N_NODES * H_CH];
__device__ __align__(128) __half  g_ah[N_NODES * H_CH];    // attn output fp16
__device__ __align__(16) unsigned g_bitmap[N_NODES * WORDS_PER_ROW];
__device__ int      g_is64;

// ---------------- prep: dtype detect + zero bitmap + fp32->fp16 cvt ----------
#define BM_U4  (N_NODES * WORDS_PER_ROW / 4)   // 524288 uint4 zeros
#define X_F4   (N_NODES * H_CH / 4)            // 524288 float4s
#define W_F4   (H_CH * H_CH / 4)               // 16384 float4s per W
#define CVT_F4 (X_F4 + 4 * W_F4)               // 589824
#define PREP_TOT (BM_U4 + CVT_F4)

__global__ void prep_kernel(const float* __restrict__ x,
                            const float* __restrict__ w0,
                            const float* __restrict__ w1,
                            const float* __restrict__ w2,
                            const float* __restrict__ w3,
                            const unsigned* __restrict__ ei_words) {
    // block 0, warp 0-3: edge dtype detection (int64 high halves all zero?)
    if (blockIdx.x == 0 && threadIdx.x < 128) {
        __shared__ int bad[4];
        int t = threadIdx.x;
        unsigned v = ei_words[2 * t + 1];
        unsigned b = __ballot_sync(0xffffffffu, v != 0u);
        if ((t & 31) == 0) bad[t >> 5] = (b != 0u);
        __syncwarp();
        if (t < 4) { /* wait via syncthreads below in same block path */ }
        __syncthreads();
        if (t == 0) g_is64 = !(bad[0] | bad[1] | bad[2] | bad[3]);
    } else if (blockIdx.x == 0) {
        __syncthreads();
    }

    for (int i = blockIdx.x * blockDim.x + threadIdx.x; i < PREP_TOT;
         i += gridDim.x * blockDim.x) {
        if (i < BM_U4) {
            ((uint4*)g_bitmap)[i] = make_uint4(0u, 0u, 0u, 0u);
        } else {
            int j = i - BM_U4;
            const float* src;
            __half* dst;
            int idx;
            if (j < X_F4) {
                src = x; dst = g_xh; idx = j;
            } else {
                int j2 = j - X_F4;
                int z = j2 >> 14;
                idx = j2 & 16383;
                src = (z == 0) ? w0 : (z == 1) ? w1 : (z == 2) ? w2 : w3;
                dst = g_wh[z];
            }
            float4 f = ((const float4*)src)[idx];
            __half2 lo = __floats2half2_rn(f.x, f.y);
            __half2 hi = __floats2half2_rn(f.z, f.w);
            uint2 packed;
            packed.x = *(uint32_t*)&lo;
            packed.y = *(uint32_t*)&hi;
            ((uint2*)dst)[idx] = packed;
        }
    }
}

// ---------------- edge scatter ----------------
__global__ void scatter_edges_kernel(const void* __restrict__ ei_raw) {
    int e = blockIdx.x * blockDim.x + threadIdx.x;
    if (e >= E_EDGES) return;
    int r, c;
    if (g_is64) {
        const long long* ei = (const long long*)ei_raw;
        r = (int)ei[e];
        c = (int)ei[E_EDGES + e];
    } else {
        const int* ei = (const int*)ei_raw;
        r = ei[e];
        c = ei[E_EDGES + e];
    }
    if ((unsigned)r < N_NODES && (unsigned)c < N_NODES)
        atomicOr(&g_bitmap[r * WORDS_PER_ROW + (c >> 5)], 1u << (c & 31));
}

// ---------------- fp16 tensor GEMM: 64-k chunks, 2-stage cp.async -------------
// m16n8k16 fp16 mma, fp32 accum; 128x64 block tile; 4 chunks of k=64.
#define SMH 72                        // half-stride per row (144B, conflict-free)
#define A_HALF (128 * SMH)            // 9216
#define B_HALF (64 * SMH)             // 4608
#define STAGE_HALF (A_HALF + B_HALF)  // 13824
#define GEMM_SMEM_BYTES (2 * STAGE_HALF * 2)   // 55296

__device__ __forceinline__ void cpa16(uint32_t dst, const __half* src) {
    asm volatile("cp.async.cg.shared.global [%0], [%1], 16;" :: "r"(dst), "l"(src));
}

__global__ __launch_bounds__(256) void gemm_f16_kernel(
        __half* __restrict__ Y0h, __half* __restrict__ Y1h, __half* __restrict__ Y2h,
        float* __restrict__ Yf, int fp32_out,
        const __half* __restrict__ A,
        const __half* __restrict__ W0, const __half* __restrict__ W1, const __half* __restrict__ W2,
        const float* __restrict__ b0p, const float* __restrict__ b1p, const float* __restrict__ b2p) {
    const int M_K = 256;
    extern __shared__ __align__(16) __half smem[];

    int z = blockIdx.z;
    const __half* W = (z == 0) ? W0 : (z == 1) ? W1 : W2;
    const float* bias = (z == 0) ? b0p : (z == 1) ? b1p : b2p;

    int tid = threadIdx.x;
    int lane = tid & 31;
    int warp = tid >> 5;
    int wm = warp & 3;
    int wn = warp >> 2;
    int mBase = blockIdx.y * 128;
    int nBase = blockIdx.x * 64;

    float c[8][4];
#pragma unroll
    for (int i = 0; i < 8; i++)
#pragma unroll
        for (int j = 0; j < 4; j++) c[i][j] = 0.f;

    int a_row = lane & 15;
    int a_colh = (lane >> 4) * 8;
    int b_row = (lane & 7) | ((lane >> 1) & 8);
    int b_colh = ((lane >> 3) & 1) * 8;

    uint32_t as_base = (uint32_t)__cvta_generic_to_shared(smem);
    uint32_t bs_base = as_base + (uint32_t)A_HALF * 2u;       // within stage 0
    uint32_t a_addr0 = as_base + ((wm * 32 + a_row) * SMH + a_colh) * 2u;
    uint32_t a_addr1 = a_addr0 + 16u * SMH * 2u;
    uint32_t b_addr0 = bs_base + ((wn * 32 + b_row) * SMH + b_colh) * 2u;
    uint32_t b_addr1 = b_addr0 + 16u * SMH * 2u;

    // cp.async: thread t -> row = t>>2 (0..63), 32B seg = (t&3)*16 halves
    int ld_row = tid >> 2;
    int ld_segh = (tid & 3) * 16;

    const __half* aSrc = A + (size_t)(mBase + ld_row) * M_K + ld_segh;
    const __half* bSrc = W + (size_t)(nBase + ld_row) * M_K + ld_segh;
    uint32_t aDst = as_base + (uint32_t)(ld_row * SMH + ld_segh) * 2u;
    uint32_t bDst = bs_base + (uint32_t)(ld_row * SMH + ld_segh) * 2u;

#define ISSUE_CHUNK(KT)                                                         \
    do {                                                                        \
        uint32_t _off = (uint32_t)((KT) & 1) * (STAGE_HALF * 2u);               \
        int _ko = (KT) * 64;                                                    \
        cpa16(aDst + _off,                       aSrc + _ko);                   \
        cpa16(aDst + _off + 16u,                 aSrc + _ko + 8);               \
        cpa16(aDst + _off + 64u * SMH * 2u,      aSrc + (size_t)64 * M_K + _ko);\
        cpa16(aDst + _off + 64u * SMH * 2u + 16u,aSrc + (size_t)64 * M_K + _ko + 8);\
        cpa16(bDst + _off,                       bSrc + _ko);                   \
        cpa16(bDst + _off + 16u,                 bSrc + _ko + 8);               \
        asm volatile("cp.async.commit_group;" ::: "memory");                    \
    } while (0)

    ISSUE_CHUNK(0);

    for (int kt = 0; kt < 4; kt++) {
        asm volatile("cp.async.wait_group 0;" ::: "memory");
        __syncthreads();
        if (kt < 3) ISSUE_CHUNK(kt + 1);

        uint32_t stOff = (uint32_t)(kt & 1) * (STAGE_HALF * 2u);
#pragma unroll
        for (int ks = 0; ks < 4; ks++) {
            uint32_t kb = (uint32_t)ks * 32u;      // 16 halves = 32 bytes per step
            uint32_t a0, a1, a2, a3, a4, a5, a6, a7;
            asm volatile(
                "ldmatrix.sync.aligned.m8n8.x4.shared.b16 {%0,%1,%2,%3}, [%4];"
                : "=r"(a0), "=r"(a1), "=r"(a2), "=r"(a3)
                : "r"(a_addr0 + stOff + kb));
            asm volatile(
                "ldmatrix.sync.aligned.m8n8.x4.shared.b16 {%0,%1,%2,%3}, [%4];"
                : "=r"(a4), "=r"(a5), "=r"(a6), "=r"(a7)
                : "r"(a_addr1 + stOff + kb));
            uint32_t bb0, bb1, bb2, bb3, bb4, bb5, bb6, bb7;
            asm volatile(
                "ldmatrix.sync.aligned.m8n8.x4.shared.b16 {%0,%1,%2,%3}, [%4];"
                : "=r"(bb0), "=r"(bb1), "=r"(bb2), "=r"(bb3)
                : "r"(b_addr0 + stOff + kb));
            asm volatile(
                "ldmatrix.sync.aligned.m8n8.x4.shared.b16 {%0,%1,%2,%3}, [%4];"
                : "=r"(bb4), "=r"(bb5), "=r"(bb6), "=r"(bb7)
                : "r"(b_addr1 + stOff + kb));

#define MMAH(CI, AA0, AA1, AA2, AA3, B0, B1)                               \
            asm volatile(                                                  \
                "mma.sync.aligned.m16n8k16.row.col.f32.f16.f16.f32 "       \
                "{%0,%1,%2,%3}, {%4,%5,%6,%7}, {%8,%9}, {%0,%1,%2,%3};"    \
                : "+f"(c[CI][0]), "+f"(c[CI][1]), "+f"(c[CI][2]), "+f"(c[CI][3]) \
                : "r"(AA0), "r"(AA1), "r"(AA2), "r"(AA3), "r"(B0), "r"(B1))
            MMAH(0, a0, a1, a2, a3, bb0, bb1);
            MMAH(1, a0, a1, a2, a3, bb2, bb3);
            MMAH(2, a0, a1, a2, a3, bb4, bb5);
            MMAH(3, a0, a1, a2, a3, bb6, bb7);
            MMAH(4, a4, a5, a6, a7, bb0, bb1);
            MMAH(5, a4, a5, a6, a7, bb2, bb3);
            MMAH(6, a4, a5, a6, a7, bb4, bb5);
            MMAH(7, a4, a5, a6, a7, bb6, bb7);
#undef MMAH
        }
    }
#undef ISSUE_CHUNK

    // epilogue
    int rowB = mBase + wm * 32 + (lane >> 2);
    __half* Yh = (z == 0) ? Y0h : (z == 1) ? Y1h : Y2h;
#pragma unroll
    for (int mt = 0; mt < 2; mt++) {
#pragma unroll
        for (int g = 0; g < 4; g++) {
            int ci = mt * 4 + g;
            int row = rowB + mt * 16;
            int col = nBase + wn * 32 + g * 8 + (lane & 3) * 2;
            float b0 = bias[col], b1 = bias[col + 1];
            float r00 = c[ci][0] + b0, r01 = c[ci][1] + b1;
            float r10 = c[ci][2] + b0, r11 = c[ci][3] + b1;
            if (fp32_out) {
                *(float2*)&Yf[(size_t)row * M_K + col] = make_float2(r00, r01);
                *(float2*)&Yf[(size_t)(row + 8) * M_K + col] = make_float2(r10, r11);
            } else {
                *(__half2*)&Yh[(size_t)row * M_K + col] = __floats2half2_rn(r00, r01);
                *(__half2*)&Yh[(size_t)(row + 8) * M_K + col] = __floats2half2_rn(r10, r11);
            }
        }
    }
}

// ---------------- sparse masked attention: warp w = head w (all fp16) ---------
__global__ __launch_bounds__(128) void attn_kernel(
        __half* __restrict__ out,
        const __half* __restrict__ qh,
        const __half* __restrict__ kh,
        const __half* __restrict__ vh) {
    __shared__ unsigned short nbr[CAP];
    __shared__ float sc[HEADS][CAP];
    __shared__ int warpSum[4];
    __shared__ int warpBase[4];
    __shared__ int deg_s;

    int i = blockIdx.x;
    int tid = threadIdx.x;          // 128 threads
    int lane = tid & 31;
    int wid = tid >> 5;             // head index

    // ---- deterministic neighbor gather ----
    uint2 wpair = *(const uint2*)&g_bitmap[i * WORDS_PER_ROW + tid * 2];
    unsigned w0 = wpair.x, w1 = wpair.y;
    int c = __popc(w0) + __popc(w1);
    int incl = c;
#pragma unroll
    for (int d = 1; d < 32; d <<= 1) {
        int n_ = __shfl_up_sync(0xffffffffu, incl, d);
        if (lane >= d) incl += n_;
    }
    if (lane == 31) warpSum[wid] = incl;
    __syncthreads();
    if (tid < 4) {
        int e = 0;
        for (int j2 = 0; j2 < tid; j2++) e += warpSum[j2];
        warpBase[tid] = e;
        if (tid == 3) deg_s = e + warpSum[3];
    }
    __syncthreads();
    int off = warpBase[wid] + (incl - c);
    int base0 = tid * 64;
    while (w0) {
        int b = __ffs(w0) - 1;
        w0 &= w0 - 1;
        if (off < CAP) nbr[off] = (unsigned short)(base0 + b);
        off++;
    }
    while (w1) {
        int b = __ffs(w1) - 1;
        w1 &= w1 - 1;
        if (off < CAP) nbr[off] = (unsigned short)(base0 + 32 + b);
        off++;
    }
    __syncthreads();
    int deg = min(deg_s, CAP);

    // ---- scores: 4 neighbors/warp-iter; 8-lane groups; one uint4 K load ----
    {
        int sub = lane >> 3;
        int chBase = (lane & 7) * 8;
        uint4 qraw = *(const uint4*)(qh + (size_t)i * H_CH + wid * HEAD_DIM + chBase);
        float2 q0 = __half22float2(*(__half2*)&qraw.x);
        float2 q1 = __half22float2(*(__half2*)&qraw.y);
        float2 q2 = __half22float2(*(__half2*)&qraw.z);
        float2 q3 = __half22float2(*(__half2*)&qraw.w);
        for (int j = 0; j < deg; j += 4) {
            int jj = j + sub;
            bool valid = (jj < deg);
            int n = nbr[valid ? jj : 0];
            uint4 raw = *(const uint4*)(kh + (size_t)n * H_CH + wid * HEAD_DIM + chBase);
            float2 f0 = __half22float2(*(__half2*)&raw.x);
            float2 f1 = __half22float2(*(__half2*)&raw.y);
            float2 f2 = __half22float2(*(__half2*)&raw.z);
            float2 f3 = __half22float2(*(__half2*)&raw.w);
            float p = f0.x * q0.x + f0.y * q0.y + f1.x * q1.x + f1.y * q1.y
                    + f2.x * q2.x + f2.y * q2.y + f3.x * q3.x + f3.y * q3.y;
            p += __shfl_xor_sync(0xffffffffu, p, 1);
            p += __shfl_xor_sync(0xffffffffu, p, 2);
            p += __shfl_xor_sync(0xffffffffu, p, 4);
            if (valid && (lane & 7) == 0) sc[wid][jj] = p * 0.125f;
        }
    }
    __syncwarp();

    // ---- warp-local softmax ----
    float m = -1e30f;
    for (int t = lane; t < deg; t += 32) m = fmaxf(m, sc[wid][t]);
#pragma unroll
    for (int d = 16; d; d >>= 1) m = fmaxf(m, __shfl_xor_sync(0xffffffffu, m, d));
    float l = 0.f;
    for (int t = lane; t < deg; t += 32) {
        float p = __expf(sc[wid][t] - m);
        sc[wid][t] = p;
        l += p;
    }
#pragma unroll
    for (int d = 16; d; d >>= 1) l += __shfl_xor_sync(0xffffffffu, l, d);
    float linv = 1.0f / l;
    __syncwarp();

    // ---- weighted V (fp16): 2 neighbors/warp-iter; fp16 output ----
    {
        int half = lane >> 4;
        int chBase = (lane & 15) * 4;
        size_t vOff = (size_t)wid * HEAD_DIM + chBase;
        float4 acc = make_float4(0.f, 0.f, 0.f, 0.f);
        for (int t = 0; t < deg; t += 2) {
            int tt = t + half;
            bool valid = (tt < deg);
            int n = nbr[valid ? tt : 0];
            float s = valid ? sc[wid][tt] : 0.f;
            uint2 raw = *(const uint2*)(vh + (size_t)n * H_CH + vOff);
            float2 f0 = __half22float2(*(__half2*)&raw.x);
            float2 f1 = __half22float2(*(__half2*)&raw.y);
            acc.x += s * f0.x; acc.y += s * f0.y;
            acc.z += s * f1.x; acc.w += s * f1.y;
        }
        acc.x += __shfl_xor_sync(0xffffffffu, acc.x, 16);
        acc.y += __shfl_xor_sync(0xffffffffu, acc.y, 16);
        acc.z += __shfl_xor_sync(0xffffffffu, acc.z, 16);
        acc.w += __shfl_xor_sync(0xffffffffu, acc.w, 16);
        if (half == 0) {
            __half2 o0 = __floats2half2_rn(acc.x * linv, acc.y * linv);
            __half2 o1 = __floats2half2_rn(acc.z * linv, acc.w * linv);
            uint2 packed;
            packed.x = *(uint32_t*)&o0;
            packed.y = *(uint32_t*)&o1;
            *(uint2*)(out + (size_t)i * H_CH + vOff) = packed;
        }
    }
}

// ---------------- launch ----------------
extern "C" void kernel_launch(void* const* d_in, const int* in_sizes, int n_in,
                              void* d_out, int out_size) {
    const float* x  = (const float*)d_in[0];
    const void*  ei = d_in[1];
    const float* Wq = (const float*)d_in[2];
    const float* bq = (const float*)d_in[3];
    const float* Wk = (const float*)d_in[4];
    const float* bk = (const float*)d_in[5];
    const float* Wv = (const float*)d_in[6];
    const float* bv = (const float*)d_in[7];
    const float* Wo = (const float*)d_in[8];
    const float* bo = (const float*)d_in[9];
    float* out = (float*)d_out;

    __half *whp, *qhp, *khp, *vhp, *ahp, *xhp;
    cudaGetSymbolAddress((void**)&xhp, g_xh);
    cudaGetSymbolAddress((void**)&whp, g_wh);
    cudaGetSymbolAddress((void**)&qhp, g_qh);
    cudaGetSymbolAddress((void**)&khp, g_kh);
    cudaGetSymbolAddress((void**)&vhp, g_vh);
    cudaGetSymbolAddress((void**)&ahp, g_ah);

    cudaFuncSetAttribute(gemm_f16_kernel,
                         cudaFuncAttributeMaxDynamicSharedMemorySize, GEMM_SMEM_BYTES);

    prep_kernel<<<2048, 256>>>(x, Wq, Wk, Wv, Wo, (const unsigned*)ei);
    scatter_edges_kernel<<<(E_EDGES + 255) / 256, 256>>>(ei);

    // fused QKV: all outputs fp16
    dim3 qkv_grid(H_CH / 64, N_NODES / 128, 3);
    gemm_f16_kernel<<<qkv_grid, 256, GEMM_SMEM_BYTES>>>(
        qhp, khp, vhp, nullptr, 0, xhp,
        whp + 0 * H_CH * H_CH, whp + 1 * H_CH * H_CH, whp + 2 * H_CH * H_CH,
        bq, bk, bv);

    attn_kernel<<<N_NODES, 128>>>(ahp, qhp, khp, vhp);

    // O-GEMM: fp32 out
    dim3 o_grid(H_CH / 64, N_NODES / 128, 1);
    gemm_f16_kernel<<<o_grid, 256, GEMM_SMEM_BYTES>>>(
        ahp, ahp, ahp, out, 1, ahp,
        whp + 3 * H_CH * H_CH, whp + 3 * H_CH * H_CH, whp + 3 * H_CH * H_CH,
        bo, bo, bo);
}

// round 16
// speedup vs baseline: 1.0244x; 1.0244x over previous
#include <cuda_runtime.h>
#include <cuda_fp16.h>
#include <stdint.h>
#include <math.h>

#define N_NODES 8192
#define H_CH 256
#define HEADS 4
#define HEAD_DIM 64
#define E_EDGES 262144
#define WORDS_PER_ROW (N_NODES / 32)   // 256
#define CAP 256

// ---------------- device scratch ----------------
__device__ __align__(128) __half  g_xh[N_NODES * H_CH];    // x in fp16
__device__ __align__(128) __half  g_wh[4][H_CH * H_CH];    // Wq,Wk,Wv,Wo fp16
__device__ __align__(128) __half  g_qh[N_NODES * H_CH];
__device__ __align__(128) __half  g_kh[N_NODES * H_CH];
__device__ __align__(128) __half  g_vh[N_NODES * H_CH];
__device__ __align__(128) __half  g_ah[N_NODES * H_CH];    // attn output fp16
__device__ __align__(16) unsigned g_bitmap[N_NODES * WORDS_PER_ROW];
__device__ int      g_is64;

// ---------------- prep: dtype detect + zero bitmap + fp32->fp16 cvt ----------
#define BM_U4  (N_NODES * WORDS_PER_ROW / 4)   // 524288 uint4 zeros
#define X_F4   (N_NODES * H_CH / 4)            // 524288 float4s
#define W_F4   (H_CH * H_CH / 4)               // 16384 float4s per W
#define CVT_F4 (X_F4 + 4 * W_F4)               // 589824
#define PREP_TOT (BM_U4 + CVT_F4)

__global__ void prep_kernel(const float* __restrict__ x,
                            const float* __restrict__ w0,
                            const float* __restrict__ w1,
                            const float* __restrict__ w2,
                            const float* __restrict__ w3,
                            const unsigned* __restrict__ ei_words) {
    if (blockIdx.x == 0 && threadIdx.x < 128) {
        __shared__ int bad[4];
        int t = threadIdx.x;
        unsigned v = ei_words[2 * t + 1];
        unsigned b = __ballot_sync(0xffffffffu, v != 0u);
        if ((t & 31) == 0) bad[t >> 5] = (b != 0u);
        __syncthreads();
        if (t == 0) g_is64 = !(bad[0] | bad[1] | bad[2] | bad[3]);
    } else if (blockIdx.x == 0) {
        __syncthreads();
    }

    for (int i = blockIdx.x * blockDim.x + threadIdx.x; i < PREP_TOT;
         i += gridDim.x * blockDim.x) {
        if (i < BM_U4) {
            ((uint4*)g_bitmap)[i] = make_uint4(0u, 0u, 0u, 0u);
        } else {
            int j = i - BM_U4;
            const float* src;
            __half* dst;
            int idx;
            if (j < X_F4) {
                src = x; dst = g_xh; idx = j;
            } else {
                int j2 = j - X_F4;
                int z = j2 >> 14;
                idx = j2 & 16383;
                src = (z == 0) ? w0 : (z == 1) ? w1 : (z == 2) ? w2 : w3;
                dst = g_wh[z];
            }
            float4 f = ((const float4*)src)[idx];
            __half2 lo = __floats2half2_rn(f.x, f.y);
            __half2 hi = __floats2half2_rn(f.z, f.w);
            uint2 packed;
            packed.x = *(uint32_t*)&lo;
            packed.y = *(uint32_t*)&hi;
            ((uint2*)dst)[idx] = packed;
        }
    }
}

// ---------------- edge scatter ----------------
__global__ void scatter_edges_kernel(const void* __restrict__ ei_raw) {
    int e = blockIdx.x * blockDim.x + threadIdx.x;
    if (e >= E_EDGES) return;
    int r, c;
    if (g_is64) {
        const long long* ei = (const long long*)ei_raw;
        r = (int)ei[e];
        c = (int)ei[E_EDGES + e];
    } else {
        const int* ei = (const int*)ei_raw;
        r = ei[e];
        c = ei[E_EDGES + e];
    }
    if ((unsigned)r < N_NODES && (unsigned)c < N_NODES)
        atomicOr(&g_bitmap[r * WORDS_PER_ROW + (c >> 5)], 1u << (c & 31));
}

// ---------------- fp16 tensor GEMM: 64-k chunks, 2-stage cp.async -------------
#define SMH 72
#define A_HALF (128 * SMH)
#define B_HALF (64 * SMH)
#define STAGE_HALF (A_HALF + B_HALF)
#define GEMM_SMEM_BYTES (2 * STAGE_HALF * 2)   // 55296

__device__ __forceinline__ void cpa16(uint32_t dst, const __half* src) {
    asm volatile("cp.async.cg.shared.global [%0], [%1], 16;" :: "r"(dst), "l"(src));
}

__global__ __launch_bounds__(256) void gemm_f16_kernel(
        __half* __restrict__ Y0h, __half* __restrict__ Y1h, __half* __restrict__ Y2h,
        float* __restrict__ Yf, int fp32_out,
        const __half* __restrict__ A,
        const __half* __restrict__ W0, const __half* __restrict__ W1, const __half* __restrict__ W2,
        const float* __restrict__ b0p, const float* __restrict__ b1p, const float* __restrict__ b2p) {
    const int M_K = 256;
    extern __shared__ __align__(16) __half smem[];

    int z = blockIdx.z;
    const __half* W = (z == 0) ? W0 : (z == 1) ? W1 : W2;
    const float* bias = (z == 0) ? b0p : (z == 1) ? b1p : b2p;

    int tid = threadIdx.x;
    int lane = tid & 31;
    int warp = tid >> 5;
    int wm = warp & 3;
    int wn = warp >> 2;
    int mBase = blockIdx.y * 128;
    int nBase = blockIdx.x * 64;

    float c[8][4];
#pragma unroll
    for (int i = 0; i < 8; i++)
#pragma unroll
        for (int j = 0; j < 4; j++) c[i][j] = 0.f;

    int a_row = lane & 15;
    int a_colh = (lane >> 4) * 8;
    int b_row = (lane & 7) | ((lane >> 1) & 8);
    int b_colh = ((lane >> 3) & 1) * 8;

    uint32_t as_base = (uint32_t)__cvta_generic_to_shared(smem);
    uint32_t bs_base = as_base + (uint32_t)A_HALF * 2u;
    uint32_t a_addr0 = as_base + ((wm * 32 + a_row) * SMH + a_colh) * 2u;
    uint32_t a_addr1 = a_addr0 + 16u * SMH * 2u;
    uint32_t b_addr0 = bs_base + ((wn * 32 + b_row) * SMH + b_colh) * 2u;
    uint32_t b_addr1 = b_addr0 + 16u * SMH * 2u;

    int ld_row = tid >> 2;
    int ld_segh = (tid & 3) * 16;

    const __half* aSrc = A + (size_t)(mBase + ld_row) * M_K + ld_segh;
    const __half* bSrc = W + (size_t)(nBase + ld_row) * M_K + ld_segh;
    uint32_t aDst = as_base + (uint32_t)(ld_row * SMH + ld_segh) * 2u;
    uint32_t bDst = bs_base + (uint32_t)(ld_row * SMH + ld_segh) * 2u;

#define ISSUE_CHUNK(KT)                                                         \
    do {                                                                        \
        uint32_t _off = (uint32_t)((KT) & 1) * (STAGE_HALF * 2u);               \
        int _ko = (KT) * 64;                                                    \
        cpa16(aDst + _off,                       aSrc + _ko);                   \
        cpa16(aDst + _off + 16u,                 aSrc + _ko + 8);               \
        cpa16(aDst + _off + 64u * SMH * 2u,      aSrc + (size_t)64 * M_K + _ko);\
        cpa16(aDst + _off + 64u * SMH * 2u + 16u,aSrc + (size_t)64 * M_K + _ko + 8);\
        cpa16(bDst + _off,                       bSrc + _ko);                   \
        cpa16(bDst + _off + 16u,                 bSrc + _ko + 8);               \
        asm volatile("cp.async.commit_group;" ::: "memory");                    \
    } while (0)

    ISSUE_CHUNK(0);

    for (int kt = 0; kt < 4; kt++) {
        asm volatile("cp.async.wait_group 0;" ::: "memory");
        __syncthreads();
        if (kt < 3) ISSUE_CHUNK(kt + 1);

        uint32_t stOff = (uint32_t)(kt & 1) * (STAGE_HALF * 2u);
#pragma unroll
        for (int ks = 0; ks < 4; ks++) {
            uint32_t kb = (uint32_t)ks * 32u;
            uint32_t a0, a1, a2, a3, a4, a5, a6, a7;
            asm volatile(
                "ldmatrix.sync.aligned.m8n8.x4.shared.b16 {%0,%1,%2,%3}, [%4];"
                : "=r"(a0), "=r"(a1), "=r"(a2), "=r"(a3)
                : "r"(a_addr0 + stOff + kb));
            asm volatile(
                "ldmatrix.sync.aligned.m8n8.x4.shared.b16 {%0,%1,%2,%3}, [%4];"
                : "=r"(a4), "=r"(a5), "=r"(a6), "=r"(a7)
                : "r"(a_addr1 + stOff + kb));
            uint32_t bb0, bb1, bb2, bb3, bb4, bb5, bb6, bb7;
            asm volatile(
                "ldmatrix.sync.aligned.m8n8.x4.shared.b16 {%0,%1,%2,%3}, [%4];"
                : "=r"(bb0), "=r"(bb1), "=r"(bb2), "=r"(bb3)
                : "r"(b_addr0 + stOff + kb));
            asm volatile(
                "ldmatrix.sync.aligned.m8n8.x4.shared.b16 {%0,%1,%2,%3}, [%4];"
                : "=r"(bb4), "=r"(bb5), "=r"(bb6), "=r"(bb7)
                : "r"(b_addr1 + stOff + kb));

#define MMAH(CI, AA0, AA1, AA2, AA3, B0, B1)                               \
            asm volatile(                                                  \
                "mma.sync.aligned.m16n8k16.row.col.f32.f16.f16.f32 "       \
                "{%0,%1,%2,%3}, {%4,%5,%6,%7}, {%8,%9}, {%0,%1,%2,%3};"    \
                : "+f"(c[CI][0]), "+f"(c[CI][1]), "+f"(c[CI][2]), "+f"(c[CI][3]) \
                : "r"(AA0), "r"(AA1), "r"(AA2), "r"(AA3), "r"(B0), "r"(B1))
            MMAH(0, a0, a1, a2, a3, bb0, bb1);
            MMAH(1, a0, a1, a2, a3, bb2, bb3);
            MMAH(2, a0, a1, a2, a3, bb4, bb5);
            MMAH(3, a0, a1, a2, a3, bb6, bb7);
            MMAH(4, a4, a5, a6, a7, bb0, bb1);
            MMAH(5, a4, a5, a6, a7, bb2, bb3);
            MMAH(6, a4, a5, a6, a7, bb4, bb5);
            MMAH(7, a4, a5, a6, a7, bb6, bb7);
#undef MMAH
        }
    }
#undef ISSUE_CHUNK

    int rowB = mBase + wm * 32 + (lane >> 2);
    __half* Yh = (z == 0) ? Y0h : (z == 1) ? Y1h : Y2h;
#pragma unroll
    for (int mt = 0; mt < 2; mt++) {
#pragma unroll
        for (int g = 0; g < 4; g++) {
            int ci = mt * 4 + g;
            int row = rowB + mt * 16;
            int col = nBase + wn * 32 + g * 8 + (lane & 3) * 2;
            float b0 = bias[col], b1 = bias[col + 1];
            float r00 = c[ci][0] + b0, r01 = c[ci][1] + b1;
            float r10 = c[ci][2] + b0, r11 = c[ci][3] + b1;
            if (fp32_out) {
                *(float2*)&Yf[(size_t)row * M_K + col] = make_float2(r00, r01);
                *(float2*)&Yf[(size_t)(row + 8) * M_K + col] = make_float2(r10, r11);
            } else {
                *(__half2*)&Yh[(size_t)row * M_K + col] = __floats2half2_rn(r00, r01);
                *(__half2*)&Yh[(size_t)(row + 8) * M_K + col] = __floats2half2_rn(r10, r11);
            }
        }
    }
}

// ---------------- sparse masked attention: warp w = head w ---------------------
// nbr[] holds PRE-SCALED offsets (node * H_CH) -> 32-bit IADD addressing.
// Score dot uses half2 HFMA2 chains (7 math ops instead of 16).
__global__ __launch_bounds__(128) void attn_kernel(
        __half* __restrict__ out,
        const __half* __restrict__ qh,
        const __half* __restrict__ kh,
        const __half* __restrict__ vh) {
    __shared__ int nbr[CAP];            // node * H_CH
    __shared__ float sc[HEADS][CAP];
    __shared__ int warpSum[4];
    __shared__ int warpBase[4];
    __shared__ int deg_s;

    int i = blockIdx.x;
    int tid = threadIdx.x;          // 128 threads
    int lane = tid & 31;
    int wid = tid >> 5;             // head index

    // ---- deterministic neighbor gather (offsets pre-scaled by H_CH) ----
    uint2 wpair = *(const uint2*)&g_bitmap[i * WORDS_PER_ROW + tid * 2];
    unsigned w0 = wpair.x, w1 = wpair.y;
    int c = __popc(w0) + __popc(w1);
    int incl = c;
#pragma unroll
    for (int d = 1; d < 32; d <<= 1) {
        int n_ = __shfl_up_sync(0xffffffffu, incl, d);
        if (lane >= d) incl += n_;
    }
    if (lane == 31) warpSum[wid] = incl;
    __syncthreads();
    if (tid < 4) {
        int e = 0;
        for (int j2 = 0; j2 < tid; j2++) e += warpSum[j2];
        warpBase[tid] = e;
        if (tid == 3) deg_s = e + warpSum[3];
    }
    __syncthreads();
    int off = warpBase[wid] + (incl - c);
    int base0 = tid * 64 * H_CH;
    while (w0) {
        int b = __ffs(w0) - 1;
        w0 &= w0 - 1;
        if (off < CAP) nbr[off] = base0 + b * H_CH;
        off++;
    }
    while (w1) {
        int b = __ffs(w1) - 1;
        w1 &= w1 - 1;
        if (off < CAP) nbr[off] = base0 + (32 + b) * H_CH;
        off++;
    }
    __syncthreads();
    int deg = min(deg_s, CAP);

    // ---- scores: 4 neighbors/warp-iter; 8-lane groups; half2 HFMA2 dot ----
    {
        int sub = lane >> 3;
        int chOff = wid * HEAD_DIM + (lane & 7) * 8;   // channel offset in row
        const __half* kBase = kh + chOff;
        uint4 qraw = *(const uint4*)(qh + i * H_CH + chOff);
        __half2 q0 = *(__half2*)&qraw.x;
        __half2 q1 = *(__half2*)&qraw.y;
        __half2 q2 = *(__half2*)&qraw.z;
        __half2 q3 = *(__half2*)&qraw.w;
        for (int j = 0; j < deg; j += 4) {
            int jj = j + sub;
            bool valid = (jj < deg);
            int noff = nbr[valid ? jj : 0];
            uint4 raw = *(const uint4*)(kBase + noff);
            __half2 p2 = __hmul2(*(__half2*)&raw.x, q0);
            p2 = __hfma2(*(__half2*)&raw.y, q1, p2);
            p2 = __hfma2(*(__half2*)&raw.z, q2, p2);
            p2 = __hfma2(*(__half2*)&raw.w, q3, p2);
            float p = __low2float(p2) + __high2float(p2);
            p += __shfl_xor_sync(0xffffffffu, p, 1);
            p += __shfl_xor_sync(0xffffffffu, p, 2);
            p += __shfl_xor_sync(0xffffffffu, p, 4);
            if (valid && (lane & 7) == 0) sc[wid][jj] = p * 0.125f;
        }
    }
    __syncwarp();

    // ---- warp-local softmax ----
    float m = -1e30f;
    for (int t = lane; t < deg; t += 32) m = fmaxf(m, sc[wid][t]);
#pragma unroll
    for (int d = 16; d; d >>= 1) m = fmaxf(m, __shfl_xor_sync(0xffffffffu, m, d));
    float l = 0.f;
    for (int t = lane; t < deg; t += 32) {
        float p = __expf(sc[wid][t] - m);
        sc[wid][t] = p;
        l += p;
    }
#pragma unroll
    for (int d = 16; d; d >>= 1) l += __shfl_xor_sync(0xffffffffu, l, d);
    float linv = 1.0f / l;
    __syncwarp();

    // ---- weighted V: 2 neighbors/warp-iter; fp32 accum; int addressing ----
    {
        int half = lane >> 4;
        int chOff = wid * HEAD_DIM + (lane & 15) * 4;
        const __half* vBase = vh + chOff;
        float4 acc = make_float4(0.f, 0.f, 0.f, 0.f);
        for (int t = 0; t < deg; t += 2) {
            int tt = t + half;
            bool valid = (tt < deg);
            int noff = nbr[valid ? tt : 0];
            float s = valid ? sc[wid][tt] : 0.f;
            uint2 raw = *(const uint2*)(vBase + noff);
            float2 f0 = __half22float2(*(__half2*)&raw.x);
            float2 f1 = __half22float2(*(__half2*)&raw.y);
            acc.x += s * f0.x; acc.y += s * f0.y;
            acc.z += s * f1.x; acc.w += s * f1.y;
        }
        acc.x += __shfl_xor_sync(0xffffffffu, acc.x, 16);
        acc.y += __shfl_xor_sync(0xffffffffu, acc.y, 16);
        acc.z += __shfl_xor_sync(0xffffffffu, acc.z, 16);
        acc.w += __shfl_xor_sync(0xffffffffu, acc.w, 16);
        if (half == 0) {
            __half2 o0 = __floats2half2_rn(acc.x * linv, acc.y * linv);
            __half2 o1 = __floats2half2_rn(acc.z * linv, acc.w * linv);
            uint2 packed;
            packed.x = *(uint32_t*)&o0;
            packed.y = *(uint32_t*)&o1;
            *(uint2*)(out + i * H_CH + chOff) = packed;
        }
    }
}

// ---------------- launch ----------------
extern "C" void kernel_launch(void* const* d_in, const int* in_sizes, int n_in,
                              void* d_out, int out_size) {
    const float* x  = (const float*)d_in[0];
    const void*  ei = d_in[1];
    const float* Wq = (const float*)d_in[2];
    const float* bq = (const float*)d_in[3];
    const float* Wk = (const float*)d_in[4];
    const float* bk = (const float*)d_in[5];
    const float* Wv = (const float*)d_in[6];
    const float* bv = (const float*)d_in[7];
    const float* Wo = (const float*)d_in[8];
    const float* bo = (const float*)d_in[9];
    float* out = (float*)d_out;

    __half *whp, *qhp, *khp, *vhp, *ahp, *xhp;
    cudaGetSymbolAddress((void**)&xhp, g_xh);
    cudaGetSymbolAddress((void**)&whp, g_wh);
    cudaGetSymbolAddress((void**)&qhp, g_qh);
    cudaGetSymbolAddress((void**)&khp, g_kh);
    cudaGetSymbolAddress((void**)&vhp, g_vh);
    cudaGetSymbolAddress((void**)&ahp, g_ah);

    cudaFuncSetAttribute(gemm_f16_kernel,
                         cudaFuncAttributeMaxDynamicSharedMemorySize, GEMM_SMEM_BYTES);

    prep_kernel<<<2048, 256>>>(x, Wq, Wk, Wv, Wo, (const unsigned*)ei);
    scatter_edges_kernel<<<(E_EDGES + 255) / 256, 256>>>(ei);

    dim3 qkv_grid(H_CH / 64, N_NODES / 128, 3);
    gemm_f16_kernel<<<qkv_grid, 256, GEMM_SMEM_BYTES>>>(
        qhp, khp, vhp, nullptr, 0, xhp,
        whp + 0 * H_CH * H_CH, whp + 1 * H_CH * H_CH, whp + 2 * H_CH * H_CH,
        bq, bk, bv);

    attn_kernel<<<N_NODES, 128>>>(ahp, qhp, khp, vhp);

    dim3 o_grid(H_CH / 64, N_NODES / 128, 1);
    gemm_f16_kernel<<<o_grid, 256, GEMM_SMEM_BYTES>>>(
        ahp, ahp, ahp, out, 1, ahp,
        whp + 3 * H_CH * H_CH, whp + 3 * H_CH * H_CH, whp + 3 * H_CH * H_CH,
        bo, bo, bo);
}

// round 17
// speedup vs baseline: 1.0593x; 1.0340x over previous
#include <cuda_runtime.h>
#include <cuda_fp16.h>
#include <stdint.h>
#include <math.h>

#define N_NODES 8192
#define H_CH 256
#define HEADS 4
#define HEAD_DIM 64
#define E_EDGES 262144
#define WORDS_PER_ROW (N_NODES / 32)   // 256
#define CAP 256

// ---------------- device scratch ----------------
__device__ __align__(128) __half  g_xh[N_NODES * H_CH];
__device__ __align__(128) __half  g_wh[4][H_CH * H_CH];
__device__ __align__(128) __half  g_qh[N_NODES * H_CH];
__device__ __align__(128) __half  g_kh[N_NODES * H_CH];
__device__ __align__(128) __half  g_vh[N_NODES * H_CH];
__device__ __align__(128) __half  g_ah[N_NODES * H_CH];
__device__ __align__(16) unsigned g_bitmap[N_NODES * WORDS_PER_ROW];
__device__ int      g_is64;

// ---------------- prep: dtype detect + zero bitmap + fp32->fp16 cvt ----------
#define BM_U4  (N_NODES * WORDS_PER_ROW / 4)
#define X_F4   (N_NODES * H_CH / 4)
#define W_F4   (H_CH * H_CH / 4)
#define CVT_F4 (X_F4 + 4 * W_F4)
#define PREP_TOT (BM_U4 + CVT_F4)

__global__ void prep_kernel(const float* __restrict__ x,
                            const float* __restrict__ w0,
                            const float* __restrict__ w1,
                            const float* __restrict__ w2,
                            const float* __restrict__ w3,
                            const unsigned* __restrict__ ei_words) {
    if (blockIdx.x == 0 && threadIdx.x < 128) {
        __shared__ int bad[4];
        int t = threadIdx.x;
        unsigned v = ei_words[2 * t + 1];
        unsigned b = __ballot_sync(0xffffffffu, v != 0u);
        if ((t & 31) == 0) bad[t >> 5] = (b != 0u);
        __syncthreads();
        if (t == 0) g_is64 = !(bad[0] | bad[1] | bad[2] | bad[3]);
    } else if (blockIdx.x == 0) {
        __syncthreads();
    }

    for (int i = blockIdx.x * blockDim.x + threadIdx.x; i < PREP_TOT;
         i += gridDim.x * blockDim.x) {
        if (i < BM_U4) {
            ((uint4*)g_bitmap)[i] = make_uint4(0u, 0u, 0u, 0u);
        } else {
            int j = i - BM_U4;
            const float* src;
            __half* dst;
            int idx;
            if (j < X_F4) {
                src = x; dst = g_xh; idx = j;
            } else {
                int j2 = j - X_F4;
                int z = j2 >> 14;
                idx = j2 & 16383;
                src = (z == 0) ? w0 : (z == 1) ? w1 : (z == 2) ? w2 : w3;
                dst = g_wh[z];
            }
            float4 f = ((const float4*)src)[idx];
            __half2 lo = __floats2half2_rn(f.x, f.y);
            __half2 hi = __floats2half2_rn(f.z, f.w);
            uint2 packed;
            packed.x = *(uint32_t*)&lo;
            packed.y = *(uint32_t*)&hi;
            ((uint2*)dst)[idx] = packed;
        }
    }
}

// ---------------- edge scatter ----------------
__global__ void scatter_edges_kernel(const void* __restrict__ ei_raw) {
    int e = blockIdx.x * blockDim.x + threadIdx.x;
    if (e >= E_EDGES) return;
    int r, c;
    if (g_is64) {
        const long long* ei = (const long long*)ei_raw;
        r = (int)ei[e];
        c = (int)ei[E_EDGES + e];
    } else {
        const int* ei = (const int*)ei_raw;
        r = ei[e];
        c = ei[E_EDGES + e];
    }
    if ((unsigned)r < N_NODES && (unsigned)c < N_NODES)
        atomicOr(&g_bitmap[r * WORDS_PER_ROW + (c >> 5)], 1u << (c & 31));
}

// ---------------- fp16 tensor GEMM: 64-k chunks, 2-stage cp.async -------------
#define SMH 72
#define A_HALF (128 * SMH)
#define B_HALF (64 * SMH)
#define STAGE_HALF (A_HALF + B_HALF)
#define GEMM_SMEM_BYTES (2 * STAGE_HALF * 2)   // 55296

__device__ __forceinline__ void cpa16(uint32_t dst, const __half* src) {
    asm volatile("cp.async.cg.shared.global [%0], [%1], 16;" :: "r"(dst), "l"(src));
}

__global__ __launch_bounds__(256) void gemm_f16_kernel(
        __half* __restrict__ Y0h, __half* __restrict__ Y1h, __half* __restrict__ Y2h,
        float* __restrict__ Yf, int fp32_out,
        const __half* __restrict__ A,
        const __half* __restrict__ W0, const __half* __restrict__ W1, const __half* __restrict__ W2,
        const float* __restrict__ b0p, const float* __restrict__ b1p, const float* __restrict__ b2p) {
    const int M_K = 256;
    extern __shared__ __align__(16) __half smem[];

    int z = blockIdx.z;
    const __half* W = (z == 0) ? W0 : (z == 1) ? W1 : W2;
    const float* bias = (z == 0) ? b0p : (z == 1) ? b1p : b2p;

    int tid = threadIdx.x;
    int lane = tid & 31;
    int warp = tid >> 5;
    int wm = warp & 3;
    int wn = warp >> 2;
    int mBase = blockIdx.y * 128;
    int nBase = blockIdx.x * 64;

    float c[8][4];
#pragma unroll
    for (int i = 0; i < 8; i++)
#pragma unroll
        for (int j = 0; j < 4; j++) c[i][j] = 0.f;

    int a_row = lane & 15;
    int a_colh = (lane >> 4) * 8;
    int b_row = (lane & 7) | ((lane >> 1) & 8);
    int b_colh = ((lane >> 3) & 1) * 8;

    uint32_t as_base = (uint32_t)__cvta_generic_to_shared(smem);
    uint32_t bs_base = as_base + (uint32_t)A_HALF * 2u;
    uint32_t a_addr0 = as_base + ((wm * 32 + a_row) * SMH + a_colh) * 2u;
    uint32_t a_addr1 = a_addr0 + 16u * SMH * 2u;
    uint32_t b_addr0 = bs_base + ((wn * 32 + b_row) * SMH + b_colh) * 2u;
    uint32_t b_addr1 = b_addr0 + 16u * SMH * 2u;

    int ld_row = tid >> 2;
    int ld_segh = (tid & 3) * 16;

    const __half* aSrc = A + (size_t)(mBase + ld_row) * M_K + ld_segh;
    const __half* bSrc = W + (size_t)(nBase + ld_row) * M_K + ld_segh;
    uint32_t aDst = as_base + (uint32_t)(ld_row * SMH + ld_segh) * 2u;
    uint32_t bDst = bs_base + (uint32_t)(ld_row * SMH + ld_segh) * 2u;

#define ISSUE_CHUNK(KT)                                                         \
    do {                                                                        \
        uint32_t _off = (uint32_t)((KT) & 1) * (STAGE_HALF * 2u);               \
        int _ko = (KT) * 64;                                                    \
        cpa16(aDst + _off,                       aSrc + _ko);                   \
        cpa16(aDst + _off + 16u,                 aSrc + _ko + 8);               \
        cpa16(aDst + _off + 64u * SMH * 2u,      aSrc + (size_t)64 * M_K + _ko);\
        cpa16(aDst + _off + 64u * SMH * 2u + 16u,aSrc + (size_t)64 * M_K + _ko + 8);\
        cpa16(bDst + _off,                       bSrc + _ko);                   \
        cpa16(bDst + _off + 16u,                 bSrc + _ko + 8);               \
        asm volatile("cp.async.commit_group;" ::: "memory");                    \
    } while (0)

    ISSUE_CHUNK(0);

    for (int kt = 0; kt < 4; kt++) {
        asm volatile("cp.async.wait_group 0;" ::: "memory");
        __syncthreads();
        if (kt < 3) ISSUE_CHUNK(kt + 1);

        uint32_t stOff = (uint32_t)(kt & 1) * (STAGE_HALF * 2u);
#pragma unroll
        for (int ks = 0; ks < 4; ks++) {
            uint32_t kb = (uint32_t)ks * 32u;
            uint32_t a0, a1, a2, a3, a4, a5, a6, a7;
            asm volatile(
                "ldmatrix.sync.aligned.m8n8.x4.shared.b16 {%0,%1,%2,%3}, [%4];"
                : "=r"(a0), "=r"(a1), "=r"(a2), "=r"(a3)
                : "r"(a_addr0 + stOff + kb));
            asm volatile(
                "ldmatrix.sync.aligned.m8n8.x4.shared.b16 {%0,%1,%2,%3}, [%4];"
                : "=r"(a4), "=r"(a5), "=r"(a6), "=r"(a7)
                : "r"(a_addr1 + stOff + kb));
            uint32_t bb0, bb1, bb2, bb3, bb4, bb5, bb6, bb7;
            asm volatile(
                "ldmatrix.sync.aligned.m8n8.x4.shared.b16 {%0,%1,%2,%3}, [%4];"
                : "=r"(bb0), "=r"(bb1), "=r"(bb2), "=r"(bb3)
                : "r"(b_addr0 + stOff + kb));
            asm volatile(
                "ldmatrix.sync.aligned.m8n8.x4.shared.b16 {%0,%1,%2,%3}, [%4];"
                : "=r"(bb4), "=r"(bb5), "=r"(bb6), "=r"(bb7)
                : "r"(b_addr1 + stOff + kb));

#define MMAH(CI, AA0, AA1, AA2, AA3, B0, B1)                               \
            asm volatile(                                                  \
                "mma.sync.aligned.m16n8k16.row.col.f32.f16.f16.f32 "       \
                "{%0,%1,%2,%3}, {%4,%5,%6,%7}, {%8,%9}, {%0,%1,%2,%3};"    \
                : "+f"(c[CI][0]), "+f"(c[CI][1]), "+f"(c[CI][2]), "+f"(c[CI][3]) \
                : "r"(AA0), "r"(AA1), "r"(AA2), "r"(AA3), "r"(B0), "r"(B1))
            MMAH(0, a0, a1, a2, a3, bb0, bb1);
            MMAH(1, a0, a1, a2, a3, bb2, bb3);
            MMAH(2, a0, a1, a2, a3, bb4, bb5);
            MMAH(3, a0, a1, a2, a3, bb6, bb7);
            MMAH(4, a4, a5, a6, a7, bb0, bb1);
            MMAH(5, a4, a5, a6, a7, bb2, bb3);
            MMAH(6, a4, a5, a6, a7, bb4, bb5);
            MMAH(7, a4, a5, a6, a7, bb6, bb7);
#undef MMAH
        }
    }
#undef ISSUE_CHUNK

    int rowB = mBase + wm * 32 + (lane >> 2);
    __half* Yh = (z == 0) ? Y0h : (z == 1) ? Y1h : Y2h;
#pragma unroll
    for (int mt = 0; mt < 2; mt++) {
#pragma unroll
        for (int g = 0; g < 4; g++) {
            int ci = mt * 4 + g;
            int row = rowB + mt * 16;
            int col = nBase + wn * 32 + g * 8 + (lane & 3) * 2;
            float b0 = bias[col], b1 = bias[col + 1];
            float r00 = c[ci][0] + b0, r01 = c[ci][1] + b1;
            float r10 = c[ci][2] + b0, r11 = c[ci][3] + b1;
            if (fp32_out) {
                *(float2*)&Yf[(size_t)row * M_K + col] = make_float2(r00, r01);
                *(float2*)&Yf[(size_t)(row + 8) * M_K + col] = make_float2(r10, r11);
            } else {
                *(__half2*)&Yh[(size_t)row * M_K + col] = __floats2half2_rn(r00, r01);
                *(__half2*)&Yh[(size_t)(row + 8) * M_K + col] = __floats2half2_rn(r10, r11);
            }
        }
    }
}

// ---------------- sparse masked attention: warp w = head w ---------------------
// Fused exp-in-score (no separate softmax pass), padded loops, 4-neighbor V.
__global__ __launch_bounds__(128) void attn_kernel(
        __half* __restrict__ out,
        const __half* __restrict__ qh,
        const __half* __restrict__ kh,
        const __half* __restrict__ vh) {
    __shared__ int nbr[CAP];            // node * H_CH, padded to multiple of 4
    __shared__ float sc[HEADS][CAP];    // exp(score); padded entries are 0
    __shared__ int warpSum[4];
    __shared__ int warpBase[4];
    __shared__ int deg_s;

    int i = blockIdx.x;
    int tid = threadIdx.x;
    int lane = tid & 31;
    int wid = tid >> 5;

    // ---- neighbor gather (offsets pre-scaled by H_CH) ----
    uint2 wpair = *(const uint2*)&g_bitmap[i * WORDS_PER_ROW + tid * 2];
    unsigned w0 = wpair.x, w1 = wpair.y;
    int c = __popc(w0) + __popc(w1);
    int incl = c;
#pragma unroll
    for (int d = 1; d < 32; d <<= 1) {
        int n_ = __shfl_up_sync(0xffffffffu, incl, d);
        if (lane >= d) incl += n_;
    }
    if (lane == 31) warpSum[wid] = incl;
    __syncthreads();
    if (tid < 4) {
        int e = 0;
        for (int j2 = 0; j2 < tid; j2++) e += warpSum[j2];
        warpBase[tid] = e;
        if (tid == 3) deg_s = e + warpSum[3];
    }
    __syncthreads();
    int off = warpBase[wid] + (incl - c);
    int base0 = tid * 64 * H_CH;
    while (w0) {
        int b = __ffs(w0) - 1;
        w0 &= w0 - 1;
        if (off < CAP) nbr[off] = base0 + b * H_CH;
        off++;
    }
    while (w1) {
        int b = __ffs(w1) - 1;
        w1 &= w1 - 1;
        if (off < CAP) nbr[off] = base0 + (32 + b) * H_CH;
        off++;
    }
    __syncthreads();
    int deg = min(deg_s, CAP);
    int degPad = (deg + 3) & ~3;
    if (tid < degPad - deg) nbr[deg + tid] = nbr[0];
    __syncthreads();

    // ---- scores + fused exp: 4 neighbors/warp-iter; 8-lane groups ----
    float lsum = 0.f;
    {
        int sub = lane >> 3;
        int chOff = wid * HEAD_DIM + (lane & 7) * 8;
        const __half* kBase = kh + chOff;
        uint4 qraw = *(const uint4*)(qh + i * H_CH + chOff);
        __half2 q0 = *(__half2*)&qraw.x;
        __half2 q1 = *(__half2*)&qraw.y;
        __half2 q2 = *(__half2*)&qraw.z;
        __half2 q3 = *(__half2*)&qraw.w;
        for (int j = 0; j < degPad; j += 4) {
            int jj = j + sub;
            int noff = nbr[jj];
            uint4 raw = *(const uint4*)(kBase + noff);
            __half2 p2 = __hmul2(*(__half2*)&raw.x, q0);
            p2 = __hfma2(*(__half2*)&raw.y, q1, p2);
            p2 = __hfma2(*(__half2*)&raw.z, q2, p2);
            p2 = __hfma2(*(__half2*)&raw.w, q3, p2);
            float p = __low2float(p2) + __high2float(p2);
            p += __shfl_xor_sync(0xffffffffu, p, 1);
            p += __shfl_xor_sync(0xffffffffu, p, 2);
            p += __shfl_xor_sync(0xffffffffu, p, 4);
            if ((lane & 7) == 0) {
                float e = (jj < deg) ? __expf(p * 0.125f) : 0.f;
                sc[wid][jj] = e;
                lsum += e;
            }
        }
    }
    // reduce l over warp (non-lead lanes contribute 0)
#pragma unroll
    for (int d = 16; d; d >>= 1) lsum += __shfl_xor_sync(0xffffffffu, lsum, d);
    float linv = 1.0f / lsum;
    __syncwarp();

    // ---- weighted V: 4 neighbors/warp-iter; 8-lane groups; 8 ch per lane ----
    {
        int sub = lane >> 3;
        int chOff = wid * HEAD_DIM + (lane & 7) * 8;
        const __half* vBase = vh + chOff;
        float acc[8];
#pragma unroll
        for (int r = 0; r < 8; r++) acc[r] = 0.f;
        for (int t = 0; t < degPad; t += 4) {
            int tt = t + sub;
            int noff = nbr[tt];
            float s = sc[wid][tt];
            uint4 raw = *(const uint4*)(vBase + noff);
            float2 f0 = __half22float2(*(__half2*)&raw.x);
            float2 f1 = __half22float2(*(__half2*)&raw.y);
            float2 f2 = __half22float2(*(__half2*)&raw.z);
            float2 f3 = __half22float2(*(__half2*)&raw.w);
            acc[0] += s * f0.x; acc[1] += s * f0.y;
            acc[2] += s * f1.x; acc[3] += s * f1.y;
            acc[4] += s * f2.x; acc[5] += s * f2.y;
            acc[6] += s * f3.x; acc[7] += s * f3.y;
        }
        // combine the 4 sub-groups (xor 8, then xor 16)
#pragma unroll
        for (int r = 0; r < 8; r++) {
            acc[r] += __shfl_xor_sync(0xffffffffu, acc[r], 8);
            acc[r] += __shfl_xor_sync(0xffffffffu, acc[r], 16);
        }
        if (lane < 8) {
            __half2 o0 = __floats2half2_rn(acc[0] * linv, acc[1] * linv);
            __half2 o1 = __floats2half2_rn(acc[2] * linv, acc[3] * linv);
            __half2 o2 = __floats2half2_rn(acc[4] * linv, acc[5] * linv);
            __half2 o3 = __floats2half2_rn(acc[6] * linv, acc[7] * linv);
            uint4 packed;
            packed.x = *(uint32_t*)&o0;
            packed.y = *(uint32_t*)&o1;
            packed.z = *(uint32_t*)&o2;
            packed.w = *(uint32_t*)&o3;
            *(uint4*)(out + i * H_CH + chOff) = packed;
        }
    }
}

// ---------------- launch ----------------
extern "C" void kernel_launch(void* const* d_in, const int* in_sizes, int n_in,
                              void* d_out, int out_size) {
    const float* x  = (const float*)d_in[0];
    const void*  ei = d_in[1];
    const float* Wq = (const float*)d_in[2];
    const float* bq = (const float*)d_in[3];
    const float* Wk = (const float*)d_in[4];
    const float* bk = (const float*)d_in[5];
    const float* Wv = (const float*)d_in[6];
    const float* bv = (const float*)d_in[7];
    const float* Wo = (const float*)d_in[8];
    const float* bo = (const float*)d_in[9];
    float* out = (float*)d_out;

    __half *whp, *qhp, *khp, *vhp, *ahp, *xhp;
    cudaGetSymbolAddress((void**)&xhp, g_xh);
    cudaGetSymbolAddress((void**)&whp, g_wh);
    cudaGetSymbolAddress((void**)&qhp, g_qh);
    cudaGetSymbolAddress((void**)&khp, g_kh);
    cudaGetSymbolAddress((void**)&vhp, g_vh);
    cudaGetSymbolAddress((void**)&ahp, g_ah);

    cudaFuncSetAttribute(gemm_f16_kernel,
                         cudaFuncAttributeMaxDynamicSharedMemorySize, GEMM_SMEM_BYTES);

    prep_kernel<<<2048, 256>>>(x, Wq, Wk, Wv, Wo, (const unsigned*)ei);
    scatter_edges_kernel<<<(E_EDGES + 255) / 256, 256>>>(ei);

    dim3 qkv_grid(H_CH / 64, N_NODES / 128, 3);
    gemm_f16_kernel<<<qkv_grid, 256, GEMM_SMEM_BYTES>>>(
        qhp, khp, vhp, nullptr, 0, xhp,
        whp + 0 * H_CH * H_CH, whp + 1 * H_CH * H_CH, whp + 2 * H_CH * H_CH,
        bq, bk, bv);

    attn_kernel<<<N_NODES, 128>>>(ahp, qhp, khp, vhp);

    dim3 o_grid(H_CH / 64, N_NODES / 128, 1);
    gemm_f16_kernel<<<o_grid, 256, GEMM_SMEM_BYTES>>>(
        ahp, ahp, ahp, out, 1, ahp,
        whp + 3 * H_CH * H_CH, whp + 3 * H_CH * H_CH, whp + 3 * H_CH * H_CH,
        bo, bo, bo);
}